// round 14
// baseline (speedup 1.0000x reference)
#include <cuda_runtime.h>
#include <cstdint>
#include <cfloat>

// Problem constants
#define BB 32
#define KK 5
#define TT 12
#define VV 50257
#define HH 512
#define NBEAMS (BB*KK)           // 160
#define NPART 32                 // v-partitions per batch row
#define PERV ((VV + NPART - 1) / NPART)   // 1571 -> ng in [392,393]
#define TPB_TOPK 256

// Output layout: ONE f32 buffer, outputs cast to f32, concatenated in
// reference return order (element offsets). Verified: rel_err == 0.
#define OFF_SEQ   ((size_t)0)                         // 32*5*13 = 2080
#define OFF_BSLP  ((size_t)2080)
#define OFF_SUM   (OFF_BSLP + (size_t)BB*KK*13*VV)    // 104536640
#define OFF_STATE (OFF_SUM + (size_t)NBEAMS)          // 104536800 (mod 4 == 0)

#define NROWS_BSLP (BB*KK*(TT+1))   // 2080
#define NROWS_STATE (2*NBEAMS)      // 320

// Scratch (static device globals; no allocation)
__device__ float g_part_val[BB * NPART * 5];
__device__ int   g_part_idx[BB * NPART * 5];
__device__ int   g_beam_ix[NBEAMS];

__device__ __forceinline__ bool better(float va, int ia, float vb, int ib) {
    return (va > vb) || (va == vb && ia < ib);
}

__device__ __forceinline__ void insert5(float val, int idx, float tv[5], int ti[5]) {
    if (better(val, idx, tv[4], ti[4])) {
        tv[4] = val; ti[4] = idx;
#pragma unroll
        for (int j = 4; j > 0; j--) {
            if (better(tv[j], ti[j], tv[j-1], ti[j-1])) {
                float fv = tv[j]; tv[j] = tv[j-1]; tv[j-1] = fv;
                int   iv = ti[j]; ti[j] = ti[j-1]; ti[j-1] = iv;
            }
        }
    }
}

// Volatile vector load: prevents CSE with pass-1 loads.
__device__ __forceinline__ float4 ldg128_nocse(const float* p) {
    float4 v;
    asm volatile("ld.global.nc.v4.f32 {%0,%1,%2,%3}, [%4];"
                 : "=f"(v.x), "=f"(v.y), "=f"(v.z), "=f"(v.w) : "l"(p));
    return v;
}

#define WARP_ARGMAX(bv, bi) \
    { _Pragma("unroll") \
      for (int s_ = 16; s_ > 0; s_ >>= 1) { \
          float ov = __shfl_xor_sync(0xFFFFFFFF, bv, s_); \
          int   oi = __shfl_xor_sync(0xFFFFFFFF, bi, s_); \
          if (better(ov, oi, bv, bi)) { bv = ov; bi = oi; } \
      } }

// ---------------------------------------------------------------------------
// Kernel 1: topk partials. grid (NPART, BB), 256 thr.
// Pass 1: 10 UNCONDITIONAL clamped LDG.128 (guaranteed MLP=10), keep only
// group maxes. Warp threshold T = 5th largest of 32 thread maxes (provably
// exact). Pass 2: reload gated groups (L2 hits), exact tiebreak inserts.
// ---------------------------------------------------------------------------
__global__ __launch_bounds__(TPB_TOPK) void topk_partial_kernel(
    const float* __restrict__ logprobs,   // (160, V)
    const float* __restrict__ bsum)       // (32, 5)
{
    const int b       = blockIdx.y;
    const int part    = blockIdx.x;
    const int tid     = threadIdx.x;
    const int lane    = tid & 31;
    const int wid     = tid >> 5;
    const int v_start = part * PERV;
    const int v_end   = min(v_start + PERV, VV);
    const int rowbase = b * KK * VV;

    float bs[KK];
#pragma unroll
    for (int k = 0; k < KK; k++) bs[k] = bsum[b * KK + k];

    // Per-k aligned scan windows (absolute element offsets; logprobs base is
    // >=256B aligned, row bases are NOT since K*V is odd).
    int s_k[KK], ng[KK];
#pragma unroll
    for (int k = 0; k < KK; k++) {
        int a0 = rowbase + k * VV + v_start;
        int a1 = rowbase + k * VV + v_end;
        int s  = (a0 + 3) & ~3;
        s_k[k] = s;
        ng[k]  = ((a1 & ~3) - s) >> 2;   // in [391, 393] -> always >= 1
    }

    // ---- Pass 1: 10 unconditional clamped loads, batched back-to-back ----
    const int ga = tid, gb = tid + TPB_TOPK;
    float4 xa[KK], xb[KK];
#pragma unroll
    for (int k = 0; k < KK; k++) {
        const int gac = min(ga, ng[k] - 1);
        const int gbc = min(gb, ng[k] - 1);
        xa[k] = *reinterpret_cast<const float4*>(logprobs + s_k[k] + 4 * gac);
        xb[k] = *reinterpret_cast<const float4*>(logprobs + s_k[k] + 4 * gbc);
    }
    float gva[KK], gvb[KK];
    float tm = -FLT_MAX;
#pragma unroll
    for (int k = 0; k < KK; k++) {
        float ma = fmaxf(fmaxf(xa[k].x, xa[k].y), fmaxf(xa[k].z, xa[k].w));
        float mb = fmaxf(fmaxf(xb[k].x, xb[k].y), fmaxf(xb[k].z, xb[k].w));
        gva[k] = (ga < ng[k]) ? (bs[k] + ma) : -FLT_MAX;
        gvb[k] = (gb < ng[k]) ? (bs[k] + mb) : -FLT_MAX;
        tm = fmaxf(tm, fmaxf(gva[k], gvb[k]));
    }

    // ---- Warp: T = 5th largest of 32 thread maxes ----
    float cur = tm, T = -FLT_MAX;
#pragma unroll
    for (int r = 0; r < 5; r++) {
        float bv = cur; int bl = lane;
#pragma unroll
        for (int s = 16; s > 0; s >>= 1) {
            float ov = __shfl_xor_sync(0xFFFFFFFF, bv, s);
            int   ol = __shfl_xor_sync(0xFFFFFFFF, bl, s);
            if (ov > bv || (ov == bv && ol < bl)) { bv = ov; bl = ol; }
        }
        if (bl == lane) cur = -FLT_MAX;
        T = bv;
    }

    // ---- Pass 2: reload gated groups (rare; L2 hits), exact inserts ----
    float tv[5]; int ti[5];
#pragma unroll
    for (int j = 0; j < 5; j++) { tv[j] = -FLT_MAX; ti[j] = 0x7FFFFFFF; }

#pragma unroll
    for (int k = 0; k < KK; k++) {
        if (gva[k] >= T) {                    // implies ga < ng[k]
            float4 x = ldg128_nocse(logprobs + s_k[k] + 4 * ga);
            const int base = s_k[k] + 4 * ga - rowbase;   // == k*VV + v
            insert5(bs[k] + x.x, base + 0, tv, ti);
            insert5(bs[k] + x.y, base + 1, tv, ti);
            insert5(bs[k] + x.z, base + 2, tv, ti);
            insert5(bs[k] + x.w, base + 3, tv, ti);
        }
        if (gvb[k] >= T) {
            float4 x = ldg128_nocse(logprobs + s_k[k] + 4 * gb);
            const int base = s_k[k] + 4 * gb - rowbase;
            insert5(bs[k] + x.x, base + 0, tv, ti);
            insert5(bs[k] + x.y, base + 1, tv, ti);
            insert5(bs[k] + x.z, base + 2, tv, ti);
            insert5(bs[k] + x.w, base + 3, tv, ti);
        }
    }

    // Head/tail scalars (<=3 each per k): threads 0..4 handle row k=tid.
    if (tid < KK) {
        int k = tid;
        int a0 = rowbase + k * VV + v_start;
        int a1 = rowbase + k * VV + v_end;
        for (int o = a0; o < s_k[k]; o++)
            insert5(bs[k] + logprobs[o], o - rowbase, tv, ti);
        for (int o = s_k[k] + 4 * ng[k]; o < a1; o++)
            insert5(bs[k] + logprobs[o], o - rowbase, tv, ti);
    }

    // ---- Warp merge of 32 lane-lists, then warp 0 merges 8 warp-lists ----
    __shared__ float swv[8 * 5];
    __shared__ int   swi[8 * 5];
    {
        float v0 = tv[0], v1 = tv[1], v2 = tv[2], v3 = tv[3], v4 = tv[4];
        int   i0 = ti[0], i1 = ti[1], i2 = ti[2], i3 = ti[3], i4 = ti[4];
#pragma unroll
        for (int r = 0; r < 5; r++) {
            float bv = v0; int bi = i0;
            WARP_ARGMAX(bv, bi)
            if (i0 == bi) {                    // flat indices unique
                v0 = v1; i0 = i1; v1 = v2; i1 = i2;
                v2 = v3; i2 = i3; v3 = v4; i3 = i4;
                v4 = -FLT_MAX; i4 = 0x7FFFFFFF;
            }
            if (lane == 0) { swv[wid * 5 + r] = bv; swi[wid * 5 + r] = bi; }
        }
    }
    __syncthreads();

    if (wid == 0) {
        float v0 = -FLT_MAX, v1 = -FLT_MAX, v2 = -FLT_MAX, v3 = -FLT_MAX, v4 = -FLT_MAX;
        int   i0 = 0x7FFFFFFF, i1 = 0x7FFFFFFF, i2 = 0x7FFFFFFF, i3 = 0x7FFFFFFF, i4 = 0x7FFFFFFF;
        if (lane < 8) {
            v0 = swv[lane*5+0]; i0 = swi[lane*5+0];
            v1 = swv[lane*5+1]; i1 = swi[lane*5+1];
            v2 = swv[lane*5+2]; i2 = swi[lane*5+2];
            v3 = swv[lane*5+3]; i3 = swi[lane*5+3];
            v4 = swv[lane*5+4]; i4 = swi[lane*5+4];
        }
        const int pbase = (b * NPART + part) * 5;
#pragma unroll
        for (int r = 0; r < 5; r++) {
            float bv = v0; int bi = i0;
            WARP_ARGMAX(bv, bi)
            if (i0 == bi && lane < 8) {
                v0 = v1; i0 = i1; v1 = v2; i1 = i2;
                v2 = v3; i2 = i3; v3 = v4; i3 = i4;
                v4 = -FLT_MAX; i4 = 0x7FFFFFFF;
            }
            if (lane == 0) { g_part_val[pbase + r] = bv; g_part_idx[pbase + r] = bi; }
        }
    }
}

// ---------------------------------------------------------------------------
// Kernel 2: final merge of 32 partials per row + small outputs.
// grid (BB), 32 threads.
// ---------------------------------------------------------------------------
__global__ __launch_bounds__(32) void topk_finish_kernel(
    const int* __restrict__ beam_seq,  // (32,5,12) int32
    float* __restrict__ out)
{
    const int b    = blockIdx.x;
    const int lane = threadIdx.x;
    const int base = (b * NPART + lane) * 5;

    float v0 = g_part_val[base+0], v1 = g_part_val[base+1], v2 = g_part_val[base+2],
          v3 = g_part_val[base+3], v4 = g_part_val[base+4];
    int   i0 = g_part_idx[base+0], i1 = g_part_idx[base+1], i2 = g_part_idx[base+2],
          i3 = g_part_idx[base+3], i4 = g_part_idx[base+4];

    int win_bi[5], win_sel[5];
    float win_v[5];
#pragma unroll
    for (int r = 0; r < 5; r++) {
        float bv = v0; int bi = i0;
        WARP_ARGMAX(bv, bi)
        if (i0 == bi) {
            v0 = v1; i0 = i1; v1 = v2; i1 = i2;
            v2 = v3; i2 = i3; v3 = v4; i3 = i4;
            v4 = -FLT_MAX; i4 = 0x7FFFFFFF;
        }
        win_v[r]   = bv;
        win_bi[r]  = bi / VV;
        win_sel[r] = bi - win_bi[r] * VV;
    }

    if (lane < 5) {
        g_beam_ix[b * KK + lane]     = win_bi[lane];
        out[OFF_SUM + b * KK + lane] = win_v[lane];
    }
    for (int idx = lane; idx < 5 * (TT + 1); idx += 32) {
        int j = idx / (TT + 1);
        int t = idx - j * (TT + 1);
        float val;
        if (t < TT) val = (float)beam_seq[(size_t)(b * KK + win_bi[j]) * TT + t];
        else        val = (float)win_sel[j];
        out[OFF_SEQ + (size_t)(b * KK + j) * (TT + 1) + t] = val;
    }
}

// ---------------------------------------------------------------------------
// Kernel 3: big gather via dual aligned __ldcs LDG.128 + component select,
// plus state gather. grid (7, 2080 + 320), 256 thr, 2048 vec per block.
// ---------------------------------------------------------------------------
__global__ __launch_bounds__(256) void gather_big_kernel(
    const float* __restrict__ bslp,    // (32,5,12,V)
    const float* __restrict__ unaug,   // (160,V)
    const float* __restrict__ state,   // (2,160,512)
    float* __restrict__ out)
{
    const int row = blockIdx.y;
    const int tid = threadIdx.x;

    if (row < NROWS_BSLP) {
        const int t   = row % (TT + 1);
        const int bk  = row / (TT + 1);
        const int b   = bk / KK;
        const int bi  = g_beam_ix[bk];

        const float* sbase; size_t soff; long slen;
        if (t < TT) {
            sbase = bslp;
            soff  = ((size_t)(b * KK + bi) * TT + t) * VV;
            slen  = (long)NBEAMS * TT * VV;
        } else {
            sbase = unaug;
            soff  = (size_t)(b * KK + bi) * VV;
            slen  = (long)NBEAMS * VV;
        }

        const size_t dst_off = OFF_BSLP + (size_t)row * VV;
        float* dst = out + dst_off;

        const int lead = (int)((4 - (dst_off & 3)) & 3);
        const int nvec = (VV - lead) >> 2;
        const int tb   = blockIdx.x * 2048;
        const int nv   = min(2048, nvec - tb);

        if (nv > 0) {
            const int  E0 = lead + 4 * tb;
            const int  ps = (int)((soff + (size_t)E0) & 3);
            const long g0 = (long)(soff + (size_t)E0) - ps;   // 16B-aligned

            if (ps == 0) {
#pragma unroll
                for (int q = 0; q < 8; q++) {
                    const int j = q * 256 + tid;
                    if (j < nv) {
                        const float4 v = __ldcs(reinterpret_cast<const float4*>(sbase + g0 + 4 * (long)j));
                        *reinterpret_cast<float4*>(dst + lead + 4 * (tb + j)) = v;
                    }
                }
            } else {
#pragma unroll 4
                for (int q = 0; q < 8; q++) {
                    const int j = q * 256 + tid;
                    if (j < nv) {
                        const long a = g0 + 4 * (long)j;
                        float4 lo, hi;
                        lo = __ldcs(reinterpret_cast<const float4*>(sbase + a));
                        if (a + 8 <= slen) {
                            hi = __ldcs(reinterpret_cast<const float4*>(sbase + a + 4));
                        } else {
                            hi.x = (a + 4 < slen) ? sbase[a + 4] : 0.0f;
                            hi.y = (a + 5 < slen) ? sbase[a + 5] : 0.0f;
                            hi.z = (a + 6 < slen) ? sbase[a + 6] : 0.0f;
                            hi.w = 0.0f;
                        }
                        float4 v;
                        if (ps == 1)      v = make_float4(lo.y, lo.z, lo.w, hi.x);
                        else if (ps == 2) v = make_float4(lo.z, lo.w, hi.x, hi.y);
                        else              v = make_float4(lo.w, hi.x, hi.y, hi.z);
                        *reinterpret_cast<float4*>(dst + lead + 4 * (tb + j)) = v;
                    }
                }
            }
        }

        // lead + tail scalars (block 0 only), direct.
        if (blockIdx.x == 0 && tid < 8) {
            const int tail_start = lead + 4 * nvec;
            if (tid < 4) {
                int v = tid;
                if (v < lead) dst[v] = sbase[soff + v];
            } else {
                int v = tail_start + (tid - 4);
                if (v < VV) dst[v] = sbase[soff + v];
            }
        }
    } else {
        if (blockIdx.x != 0) return;
        const int r2 = row - NROWS_BSLP;      // 0..319
        const int s  = r2 / NBEAMS;
        const int j  = r2 - s * NBEAMS;
        const int b  = j / KK;
        const int bi = g_beam_ix[j];

        const float4* src = reinterpret_cast<const float4*>(
            state + (size_t)s * NBEAMS * HH + (size_t)(b * KK + bi) * HH);
        float4* dst = reinterpret_cast<float4*>(
            out + OFF_STATE + (size_t)r2 * HH);
        if (tid < HH / 4)
            dst[tid] = src[tid];
    }
}

// ---------------------------------------------------------------------------
extern "C" void kernel_launch(void* const* d_in, const int* in_sizes, int n_in,
                              void* d_out, int out_size) {
    const float* logprobs = (const float*)d_in[0];       // (160, V)
    const float* unaug    = (const float*)d_in[1];       // (160, V)
    const int*   beam_seq = (const int*)d_in[2];         // (32,5,12) int32
    const float* bslp     = (const float*)d_in[3];       // (32,5,12,V)
    const float* bsum     = (const float*)d_in[4];       // (32,5)
    const float* state    = (const float*)d_in[5];       // (2,160,512)
    // d_in[6] = bdash (=5), hardcoded

    float* out = (float*)d_out;

    {
        dim3 grid(NPART, BB);   // (32, 32) = 1024 blocks
        topk_partial_kernel<<<grid, TPB_TOPK>>>(logprobs, bsum);
    }
    topk_finish_kernel<<<BB, 32>>>(beam_seq, out);
    {
        dim3 grid(7, NROWS_BSLP + NROWS_STATE);   // 2048 vec/block
        gather_big_kernel<<<grid, 256>>>(bslp, unaug, state, out);
    }
}

// round 15
// speedup vs baseline: 1.1788x; 1.1788x over previous
#include <cuda_runtime.h>
#include <cstdint>
#include <cfloat>

// Problem constants
#define BB 32
#define KK 5
#define TT 12
#define VV 50257
#define HH 512
#define NBEAMS (BB*KK)           // 160
#define NPART 32                 // v-partitions per batch row
#define PERV ((VV + NPART - 1) / NPART)   // 1571 -> ng in [391,393]
#define TPB_TOPK 256

// Output layout: ONE f32 buffer, outputs cast to f32, concatenated in
// reference return order (element offsets). Verified: rel_err == 0.
#define OFF_SEQ   ((size_t)0)                         // 32*5*13 = 2080
#define OFF_BSLP  ((size_t)2080)
#define OFF_SUM   (OFF_BSLP + (size_t)BB*KK*13*VV)    // 104536640
#define OFF_STATE (OFF_SUM + (size_t)NBEAMS)          // 104536800 (mod 4 == 0)

#define NROWS_BSLP (BB*KK*(TT+1))   // 2080
#define NROWS_STATE (2*NBEAMS)      // 320

// Scratch (static device globals; no allocation)
__device__ float g_part_val[BB * NPART * 5];
__device__ int   g_part_idx[BB * NPART * 5];
__device__ int   g_beam_ix[NBEAMS];
__device__ unsigned int g_done[BB];   // zero-init; reset after each use

__device__ __forceinline__ bool better(float va, int ia, float vb, int ib) {
    return (va > vb) || (va == vb && ia < ib);
}

__device__ __forceinline__ void insert5(float val, int idx, float tv[5], int ti[5]) {
    if (better(val, idx, tv[4], ti[4])) {
        tv[4] = val; ti[4] = idx;
#pragma unroll
        for (int j = 4; j > 0; j--) {
            if (better(tv[j], ti[j], tv[j-1], ti[j-1])) {
                float fv = tv[j]; tv[j] = tv[j-1]; tv[j-1] = fv;
                int   iv = ti[j]; ti[j] = ti[j-1]; ti[j-1] = iv;
            }
        }
    }
}

// Order-preserving float -> uint key (monotone: a<b <=> key(a)<key(b)).
__device__ __forceinline__ unsigned fkey(float f) {
    unsigned u = __float_as_uint(f);
    return (u & 0x80000000u) ? ~u : (u | 0x80000000u);
}

// Volatile vector load: prevents CSE with pass-1 loads.
__device__ __forceinline__ float4 ldg128_nocse(const float* p) {
    float4 v;
    asm volatile("ld.global.nc.v4.f32 {%0,%1,%2,%3}, [%4];"
                 : "=f"(v.x), "=f"(v.y), "=f"(v.z), "=f"(v.w) : "l"(p));
    return v;
}

#define WARP_ARGMAX(bv, bi) \
    { _Pragma("unroll") \
      for (int s_ = 16; s_ > 0; s_ >>= 1) { \
          float ov = __shfl_xor_sync(0xFFFFFFFF, bv, s_); \
          int   oi = __shfl_xor_sync(0xFFFFFFFF, bi, s_); \
          if (better(ov, oi, bv, bi)) { bv = ov; bi = oi; } \
      } }

// ---------------------------------------------------------------------------
// Kernel 1: topk partials + fused final merge. grid (NPART, BB), 256 thr.
// Pass 1: two scopes of 5 batched clamped LDG.128, reduced to maxes in-scope
// (no float4 residency across scopes -> no spills). Warp threshold = 5th
// largest of 32 thread maxes via REDUX on orderable keys (provably exact).
// Pass 2: reload gated groups (L2 hits), exact tiebreak inserts.
// ---------------------------------------------------------------------------
__global__ __launch_bounds__(TPB_TOPK) void topk_kernel(
    const float* __restrict__ logprobs,   // (160, V)
    const float* __restrict__ bsum,       // (32, 5)
    const int*   __restrict__ beam_seq,   // (32,5,12) int32
    float* __restrict__ out)
{
    const int b       = blockIdx.y;
    const int part    = blockIdx.x;
    const int tid     = threadIdx.x;
    const int lane    = tid & 31;
    const int wid     = tid >> 5;
    const int v_start = part * PERV;
    const int v_end   = min(v_start + PERV, VV);
    const int rowbase = b * KK * VV;

    float bs[KK];
#pragma unroll
    for (int k = 0; k < KK; k++) bs[k] = bsum[b * KK + k];

    // Per-k aligned scan windows (absolute element offsets; logprobs base is
    // >=256B aligned, row bases are NOT since K*V is odd).
    int s_k[KK], ng[KK];
#pragma unroll
    for (int k = 0; k < KK; k++) {
        int a0 = rowbase + k * VV + v_start;
        int a1 = rowbase + k * VV + v_end;
        int s  = (a0 + 3) & ~3;
        s_k[k] = s;
        ng[k]  = ((a1 & ~3) - s) >> 2;   // in [391, 393] -> always >= 1
    }

    const int ga = tid, gb = tid + TPB_TOPK;
    float gva[KK], gvb[KK];

    // ---- Pass 1, scope A: 5 batched loads -> maxes (float4s die here) ----
    {
        float4 t0 = *reinterpret_cast<const float4*>(logprobs + s_k[0] + 4 * min(ga, ng[0]-1));
        float4 t1 = *reinterpret_cast<const float4*>(logprobs + s_k[1] + 4 * min(ga, ng[1]-1));
        float4 t2 = *reinterpret_cast<const float4*>(logprobs + s_k[2] + 4 * min(ga, ng[2]-1));
        float4 t3 = *reinterpret_cast<const float4*>(logprobs + s_k[3] + 4 * min(ga, ng[3]-1));
        float4 t4 = *reinterpret_cast<const float4*>(logprobs + s_k[4] + 4 * min(ga, ng[4]-1));
        gva[0] = fmaxf(fmaxf(t0.x, t0.y), fmaxf(t0.z, t0.w));
        gva[1] = fmaxf(fmaxf(t1.x, t1.y), fmaxf(t1.z, t1.w));
        gva[2] = fmaxf(fmaxf(t2.x, t2.y), fmaxf(t2.z, t2.w));
        gva[3] = fmaxf(fmaxf(t3.x, t3.y), fmaxf(t3.z, t3.w));
        gva[4] = fmaxf(fmaxf(t4.x, t4.y), fmaxf(t4.z, t4.w));
    }
    // ---- Pass 1, scope B ----
    {
        float4 t0 = *reinterpret_cast<const float4*>(logprobs + s_k[0] + 4 * min(gb, ng[0]-1));
        float4 t1 = *reinterpret_cast<const float4*>(logprobs + s_k[1] + 4 * min(gb, ng[1]-1));
        float4 t2 = *reinterpret_cast<const float4*>(logprobs + s_k[2] + 4 * min(gb, ng[2]-1));
        float4 t3 = *reinterpret_cast<const float4*>(logprobs + s_k[3] + 4 * min(gb, ng[3]-1));
        float4 t4 = *reinterpret_cast<const float4*>(logprobs + s_k[4] + 4 * min(gb, ng[4]-1));
        gvb[0] = fmaxf(fmaxf(t0.x, t0.y), fmaxf(t0.z, t0.w));
        gvb[1] = fmaxf(fmaxf(t1.x, t1.y), fmaxf(t1.z, t1.w));
        gvb[2] = fmaxf(fmaxf(t2.x, t2.y), fmaxf(t2.z, t2.w));
        gvb[3] = fmaxf(fmaxf(t3.x, t3.y), fmaxf(t3.z, t3.w));
        gvb[4] = fmaxf(fmaxf(t4.x, t4.y), fmaxf(t4.z, t4.w));
    }

    float tm = -FLT_MAX;
#pragma unroll
    for (int k = 0; k < KK; k++) {
        gva[k] = (ga < ng[k]) ? (bs[k] + gva[k]) : -FLT_MAX;
        gvb[k] = (gb < ng[k]) ? (bs[k] + gvb[k]) : -FLT_MAX;
        tm = fmaxf(tm, fmaxf(gva[k], gvb[k]));
    }

    // ---- Warp: Tk = key of 5th largest thread max (REDUX + ballot) ----
    unsigned curk = fkey(tm), Tk = 0;
#pragma unroll
    for (int r = 0; r < 5; r++) {
        unsigned m = __reduce_max_sync(0xFFFFFFFF, curk);
        Tk = m;
        unsigned ball = __ballot_sync(0xFFFFFFFF, curk == m);
        if (lane == __ffs(ball) - 1) curk = 0u;
    }

    // ---- Pass 2: reload gated groups (rare; L2 hits), exact inserts ----
    float tv[5]; int ti[5];
#pragma unroll
    for (int j = 0; j < 5; j++) { tv[j] = -FLT_MAX; ti[j] = 0x7FFFFFFF; }

#pragma unroll
    for (int k = 0; k < KK; k++) {
        if (fkey(gva[k]) >= Tk && ga < ng[k]) {
            float4 x = ldg128_nocse(logprobs + s_k[k] + 4 * ga);
            const int base = s_k[k] + 4 * ga - rowbase;   // == k*VV + v
            insert5(bs[k] + x.x, base + 0, tv, ti);
            insert5(bs[k] + x.y, base + 1, tv, ti);
            insert5(bs[k] + x.z, base + 2, tv, ti);
            insert5(bs[k] + x.w, base + 3, tv, ti);
        }
        if (fkey(gvb[k]) >= Tk && gb < ng[k]) {
            float4 x = ldg128_nocse(logprobs + s_k[k] + 4 * gb);
            const int base = s_k[k] + 4 * gb - rowbase;
            insert5(bs[k] + x.x, base + 0, tv, ti);
            insert5(bs[k] + x.y, base + 1, tv, ti);
            insert5(bs[k] + x.z, base + 2, tv, ti);
            insert5(bs[k] + x.w, base + 3, tv, ti);
        }
    }

    // Head/tail scalars (<=3 each per k): threads 0..4 handle row k=tid.
    if (tid < KK) {
        int k = tid;
        int a0 = rowbase + k * VV + v_start;
        int a1 = rowbase + k * VV + v_end;
        for (int o = a0; o < s_k[k]; o++)
            insert5(bs[k] + logprobs[o], o - rowbase, tv, ti);
        for (int o = s_k[k] + 4 * ng[k]; o < a1; o++)
            insert5(bs[k] + logprobs[o], o - rowbase, tv, ti);
    }

    // ---- Warp merge of 32 lane-lists, then warp 0 merges 8 warp-lists ----
    __shared__ float swv[8 * 5];
    __shared__ int   swi[8 * 5];
    {
        float v0 = tv[0], v1 = tv[1], v2 = tv[2], v3 = tv[3], v4 = tv[4];
        int   i0 = ti[0], i1 = ti[1], i2 = ti[2], i3 = ti[3], i4 = ti[4];
#pragma unroll
        for (int r = 0; r < 5; r++) {
            float bv = v0; int bi = i0;
            WARP_ARGMAX(bv, bi)
            if (i0 == bi) {                    // flat indices unique
                v0 = v1; i0 = i1; v1 = v2; i1 = i2;
                v2 = v3; i2 = i3; v3 = v4; i3 = i4;
                v4 = -FLT_MAX; i4 = 0x7FFFFFFF;
            }
            if (lane == 0) { swv[wid * 5 + r] = bv; swi[wid * 5 + r] = bi; }
        }
    }
    __syncthreads();

    if (wid == 0) {
        float v0 = -FLT_MAX, v1 = -FLT_MAX, v2 = -FLT_MAX, v3 = -FLT_MAX, v4 = -FLT_MAX;
        int   i0 = 0x7FFFFFFF, i1 = 0x7FFFFFFF, i2 = 0x7FFFFFFF, i3 = 0x7FFFFFFF, i4 = 0x7FFFFFFF;
        if (lane < 8) {
            v0 = swv[lane*5+0]; i0 = swi[lane*5+0];
            v1 = swv[lane*5+1]; i1 = swi[lane*5+1];
            v2 = swv[lane*5+2]; i2 = swi[lane*5+2];
            v3 = swv[lane*5+3]; i3 = swi[lane*5+3];
            v4 = swv[lane*5+4]; i4 = swi[lane*5+4];
        }
        const int pbase = (b * NPART + part) * 5;
#pragma unroll
        for (int r = 0; r < 5; r++) {
            float bv = v0; int bi = i0;
            WARP_ARGMAX(bv, bi)
            if (i0 == bi && lane < 8) {
                v0 = v1; i0 = i1; v1 = v2; i1 = i2;
                v2 = v3; i2 = i3; v3 = v4; i3 = i4;
                v4 = -FLT_MAX; i4 = 0x7FFFFFFF;
            }
            if (lane == 0) { g_part_val[pbase + r] = bv; g_part_idx[pbase + r] = bi; }
        }

        unsigned int old = 0;
        if (lane == 0) {
            __threadfence();
            old = atomicAdd(&g_done[b], 1u);
        }
        old = __shfl_sync(0xFFFFFFFF, old, 0);

        if (old == NPART - 1) {
            // Last block for this row: merge 32 partials, emit outputs.
            __threadfence();   // acquire
            const int base = (b * NPART + lane) * 5;
            float u0 = g_part_val[base+0], u1 = g_part_val[base+1], u2 = g_part_val[base+2],
                  u3 = g_part_val[base+3], u4 = g_part_val[base+4];
            int   j0 = g_part_idx[base+0], j1 = g_part_idx[base+1], j2 = g_part_idx[base+2],
                  j3 = g_part_idx[base+3], j4 = g_part_idx[base+4];

            int win_bi[5], win_sel[5];
            float win_v[5];
#pragma unroll
            for (int r = 0; r < 5; r++) {
                float bv = u0; int bi = j0;
                WARP_ARGMAX(bv, bi)
                if (j0 == bi) {
                    u0 = u1; j0 = j1; u1 = u2; j1 = j2;
                    u2 = u3; j2 = j3; u3 = u4; j3 = j4;
                    u4 = -FLT_MAX; j4 = 0x7FFFFFFF;
                }
                win_v[r]   = bv;
                win_bi[r]  = bi / VV;
                win_sel[r] = bi - win_bi[r] * VV;
            }

            if (lane < 5) {
                g_beam_ix[b * KK + lane]     = win_bi[lane];
                out[OFF_SUM + b * KK + lane] = win_v[lane];
            }
            for (int idx = lane; idx < 5 * (TT + 1); idx += 32) {
                int j = idx / (TT + 1);
                int t = idx - j * (TT + 1);
                float val;
                if (t < TT) val = (float)beam_seq[(size_t)(b * KK + win_bi[j]) * TT + t];
                else        val = (float)win_sel[j];
                out[OFF_SEQ + (size_t)(b * KK + j) * (TT + 1) + t] = val;
            }
            if (lane == 0) g_done[b] = 0;   // reset for next graph replay
        }
    }
}

// ---------------------------------------------------------------------------
// Kernel 2: big gather via dual aligned LDG.128 + component select (ps is
// row-uniform), plus state gather. grid (13, 2080 + 320), 256 thr.
// EXACT R10 form — best measured twice: 85.2us @ 5.78 TB/s. Do not touch.
// ---------------------------------------------------------------------------
__global__ __launch_bounds__(256) void gather_big_kernel(
    const float* __restrict__ bslp,    // (32,5,12,V)
    const float* __restrict__ unaug,   // (160,V)
    const float* __restrict__ state,   // (2,160,512)
    float* __restrict__ out)
{
    const int row = blockIdx.y;
    const int tid = threadIdx.x;

    if (row < NROWS_BSLP) {
        const int t   = row % (TT + 1);
        const int bk  = row / (TT + 1);
        const int b   = bk / KK;
        const int bi  = g_beam_ix[bk];

        const float* sbase; size_t soff; long slen;
        if (t < TT) {
            sbase = bslp;
            soff  = ((size_t)(b * KK + bi) * TT + t) * VV;
            slen  = (long)NBEAMS * TT * VV;
        } else {
            sbase = unaug;
            soff  = (size_t)(b * KK + bi) * VV;
            slen  = (long)NBEAMS * VV;
        }

        const size_t dst_off = OFF_BSLP + (size_t)row * VV;
        float* dst = out + dst_off;

        const int lead = (int)((4 - (dst_off & 3)) & 3);
        const int nvec = (VV - lead) >> 2;
        const int tb   = blockIdx.x * 1024;
        const int nv   = min(1024, nvec - tb);

        if (nv > 0) {
            const int  E0 = lead + 4 * tb;
            const int  ps = (int)((soff + (size_t)E0) & 3);
            const long g0 = (long)(soff + (size_t)E0) - ps;   // 16B-aligned

            if (ps == 0) {
#pragma unroll
                for (int q = 0; q < 4; q++) {
                    const int j = q * 256 + tid;
                    if (j < nv) {
                        const float4 v = *reinterpret_cast<const float4*>(sbase + g0 + 4 * (long)j);
                        *reinterpret_cast<float4*>(dst + lead + 4 * (tb + j)) = v;
                    }
                }
            } else {
#pragma unroll
                for (int q = 0; q < 4; q++) {
                    const int j = q * 256 + tid;
                    if (j < nv) {
                        const long a = g0 + 4 * (long)j;
                        float4 lo, hi;
                        lo = *reinterpret_cast<const float4*>(sbase + a);
                        if (a + 8 <= slen) {
                            hi = *reinterpret_cast<const float4*>(sbase + a + 4);
                        } else {
                            hi.x = (a + 4 < slen) ? sbase[a + 4] : 0.0f;
                            hi.y = (a + 5 < slen) ? sbase[a + 5] : 0.0f;
                            hi.z = (a + 6 < slen) ? sbase[a + 6] : 0.0f;
                            hi.w = 0.0f;
                        }
                        float4 v;
                        if (ps == 1)      v = make_float4(lo.y, lo.z, lo.w, hi.x);
                        else if (ps == 2) v = make_float4(lo.z, lo.w, hi.x, hi.y);
                        else              v = make_float4(lo.w, hi.x, hi.y, hi.z);
                        *reinterpret_cast<float4*>(dst + lead + 4 * (tb + j)) = v;
                    }
                }
            }
        }

        // lead + tail scalars (block 0 only), direct.
        if (blockIdx.x == 0 && tid < 8) {
            const int tail_start = lead + 4 * nvec;
            if (tid < 4) {
                int v = tid;
                if (v < lead) dst[v] = sbase[soff + v];
            } else {
                int v = tail_start + (tid - 4);
                if (v < VV) dst[v] = sbase[soff + v];
            }
        }
    } else {
        if (blockIdx.x != 0) return;
        const int r2 = row - NROWS_BSLP;      // 0..319
        const int s  = r2 / NBEAMS;
        const int j  = r2 - s * NBEAMS;
        const int b  = j / KK;
        const int bi = g_beam_ix[j];

        const float4* src = reinterpret_cast<const float4*>(
            state + (size_t)s * NBEAMS * HH + (size_t)(b * KK + bi) * HH);
        float4* dst = reinterpret_cast<float4*>(
            out + OFF_STATE + (size_t)r2 * HH);
        if (tid < HH / 4)
            dst[tid] = src[tid];
    }
}

// ---------------------------------------------------------------------------
extern "C" void kernel_launch(void* const* d_in, const int* in_sizes, int n_in,
                              void* d_out, int out_size) {
    const float* logprobs = (const float*)d_in[0];       // (160, V)
    const float* unaug    = (const float*)d_in[1];       // (160, V)
    const int*   beam_seq = (const int*)d_in[2];         // (32,5,12) int32
    const float* bslp     = (const float*)d_in[3];       // (32,5,12,V)
    const float* bsum     = (const float*)d_in[4];       // (32,5)
    const float* state    = (const float*)d_in[5];       // (2,160,512)
    // d_in[6] = bdash (=5), hardcoded

    float* out = (float*)d_out;

    {
        dim3 grid(NPART, BB);   // (32, 32) = 1024 blocks
        topk_kernel<<<grid, TPB_TOPK>>>(logprobs, bsum, beam_seq, out);
    }
    {
        dim3 grid(13, NROWS_BSLP + NROWS_STATE);
        gather_big_kernel<<<grid, 256>>>(bslp, unaug, state, out);
    }
}